// round 14
// baseline (speedup 1.0000x reference)
#include <cuda_runtime.h>
#include <cuda_bf16.h>
#include <cstdint>

#define NP 4096
#define NL 2048
#define DM 512
#define NH 8
#define DK 64
#define NB 16
#define MAXT 80   // max row tiles: 4096/64 + 16

// Scratch (allocation-free rule: __device__ globals)
__device__ float g_Q[NP * DM];
__device__ float g_K[NL * DM];
__device__ float g_V[NL * DM];
__device__ float g_ctx[NP * DM];
__device__ float g_tmp[NP * DM];
__device__ int   g_bp[NP];
__device__ int   g_bl[NL];
__device__ int   g_pstart[NB], g_pend[NB];
__device__ int   g_lstart[NB], g_lend[NB];
__device__ int   g_tile_b[MAXT], g_tile_r[MAXT];

__device__ __forceinline__ float to_tf32(float x) {
    float y;
    asm("cvt.rna.tf32.f32 %0, %1;" : "=f"(y) : "f"(x));
    return y;
}

#define MMA_TF32(d, a, b) \
    asm volatile("mma.sync.aligned.m16n8k8.row.col.f32.tf32.tf32.f32 " \
        "{%0,%1,%2,%3}, {%4,%5,%6,%7}, {%8,%9}, {%0,%1,%2,%3};" \
        : "+f"((d)[0]), "+f"((d)[1]), "+f"((d)[2]), "+f"((d)[3]) \
        : "r"((a)[0]), "r"((a)[1]), "r"((a)[2]), "r"((a)[3]), \
          "r"((b)[0]), "r"((b)[1]))

__device__ __forceinline__ void cp16(void* sdst, const void* gsrc) {
    uint32_t s = (uint32_t)__cvta_generic_to_shared(sdst);
    asm volatile("cp.async.ca.shared.global [%0], [%1], 16;" :: "r"(s), "l"(gsrc) : "memory");
}
#define CP_COMMIT() asm volatile("cp.async.commit_group;" ::: "memory")
#define CP_WAIT(n)  asm volatile("cp.async.wait_group %0;" :: "n"(n) : "memory")

// ---------------------------------------------------------------------------
// tf32 mma GEMM tile, cp.async 3-stage pipelined.
// Y[64,64] = X[64,K] W[64,K]^T + bias (+res). 128 threads, 4 warps (2x2),
// warp tile 32x32. Small tile -> many CTAs/SM + 3.5 waves for latency hiding.
// ---------------------------------------------------------------------------
#define GK   16
#define GPAD 20
#define NSTG 3

__device__ __forceinline__ void gemm_tile(const float* __restrict__ X,
                                          const float* __restrict__ W,
                                          const float* __restrict__ bias,
                                          const float* __restrict__ res,
                                          float* __restrict__ Y,
                                          int row0, int col0)
{
    __shared__ __align__(16) float Xs[NSTG][64 * GPAD];
    __shared__ __align__(16) float Ws[NSTG][64 * GPAD];

    const int t = threadIdx.x;               // 0..127
    const int lane = t & 31, w = t >> 5;     // 4 warps
    const int wm = w >> 1, wn = w & 1;       // 2 x 2 warp grid
    const int m0 = wm * 32, n0 = wn * 32;
    const int gid = lane >> 2, q4 = lane & 3;

    float d[2][4][4] = {};

    // stage chunk: X 64x16 = 256 float4, W 64x16 = 256 float4; 128 threads
    auto stage = [&](int buf, int k0) {
        #pragma unroll
        for (int j = 0; j < 2; j++) {
            const int f = t + j * 128;        // 0..255
            const int r = f >> 2, q = (f & 3) * 4;
            cp16(&Xs[buf][r * GPAD + q], X + (size_t)(row0 + r) * DM + k0 + q);
            cp16(&Ws[buf][r * GPAD + q], W + (size_t)(col0 + r) * DM + k0 + q);
        }
    };

    const int NCH = DM / GK;   // 32 chunks
    stage(0, 0); CP_COMMIT();
    stage(1, GK); CP_COMMIT();

    for (int kc = 0; kc < NCH; kc++) {
        const int buf = kc % NSTG;
        if (kc + 2 < NCH) {
            stage((kc + 2) % NSTG, (kc + 2) * GK);
            CP_COMMIT();
            CP_WAIT(2);
        } else if (kc + 1 < NCH) {
            CP_WAIT(1);
        } else {
            CP_WAIT(0);
        }
        __syncthreads();

        #pragma unroll
        for (int kk = 0; kk < GK; kk += 8) {
            uint32_t a[2][4], b[4][2];
            #pragma unroll
            for (int mt = 0; mt < 2; mt++) {
                const int rb = m0 + mt * 16 + gid;
                a[mt][0] = __float_as_uint(Xs[buf][rb * GPAD + kk + q4]);
                a[mt][1] = __float_as_uint(Xs[buf][(rb + 8) * GPAD + kk + q4]);
                a[mt][2] = __float_as_uint(Xs[buf][rb * GPAD + kk + q4 + 4]);
                a[mt][3] = __float_as_uint(Xs[buf][(rb + 8) * GPAD + kk + q4 + 4]);
            }
            #pragma unroll
            for (int nt = 0; nt < 4; nt++) {
                const int nb = n0 + nt * 8 + gid;
                b[nt][0] = __float_as_uint(Ws[buf][nb * GPAD + kk + q4]);
                b[nt][1] = __float_as_uint(Ws[buf][nb * GPAD + kk + q4 + 4]);
            }
            #pragma unroll
            for (int mt = 0; mt < 2; mt++)
                #pragma unroll
                for (int nt = 0; nt < 4; nt++)
                    MMA_TF32(d[mt][nt], a[mt], b[nt]);
        }
        __syncthreads();           // WAR: buffer reuse safe
    }

    #pragma unroll
    for (int mt = 0; mt < 2; mt++) {
        #pragma unroll
        for (int nt = 0; nt < 4; nt++) {
            const int r1 = row0 + m0 + mt * 16 + gid;
            const int c  = col0 + n0 + nt * 8 + q4 * 2;
            const float b0 = bias[c], b1 = bias[c + 1];
            float2 o0 = make_float2(d[mt][nt][0] + b0, d[mt][nt][1] + b1);
            float2 o1 = make_float2(d[mt][nt][2] + b0, d[mt][nt][3] + b1);
            if (res) {
                const float2 r0v = *reinterpret_cast<const float2*>(res + (size_t)r1 * DM + c);
                const float2 r1v = *reinterpret_cast<const float2*>(res + (size_t)(r1 + 8) * DM + c);
                o0.x += r0v.x; o0.y += r0v.y;
                o1.x += r1v.x; o1.y += r1v.y;
            }
            *reinterpret_cast<float2*>(Y + (size_t)r1 * DM + c) = o0;
            *reinterpret_cast<float2*>(Y + (size_t)(r1 + 8) * DM + c) = o1;
        }
    }
}

// ---------------------------------------------------------------------------
// Phase 1 fused kernel (128 threads):
//   CTAs [0,1024)         : Q/K/V projections (64x64 tiles; Q:512, K:256, V:256)
//   CTAs [1024, 1024+4096): zero-fill of attn output (DRAM-bound)
//   CTA  5120             : batch prep (dtype normalize, ranges, worklist)
// ---------------------------------------------------------------------------
__global__ void __launch_bounds__(128) p1_kernel(
    const float* __restrict__ protein, const float* __restrict__ ligand,
    const int* __restrict__ bpraw, const int* __restrict__ blraw,
    const float* __restrict__ Wq, const float* __restrict__ bq,
    const float* __restrict__ Wk, const float* __restrict__ bk,
    const float* __restrict__ Wv, const float* __restrict__ bv,
    float* __restrict__ Qp, float* __restrict__ Kp, float* __restrict__ Vp,
    float4* __restrict__ attn4)
{
    const int bx = blockIdx.x;
    const int t = threadIdx.x;
    if (bx < 1024) {
        const float *X, *W, *bias; float* Y; int lb;
        if (bx < 512)      { X = protein; W = Wq; bias = bq; Y = Qp; lb = bx; }
        else if (bx < 768) { X = ligand;  W = Wk; bias = bk; Y = Kp; lb = bx - 512; }
        else               { X = ligand;  W = Wv; bias = bv; Y = Vp; lb = bx - 768; }
        gemm_tile(X, W, bias, nullptr, Y, (lb >> 3) * 64, (lb & 7) * 64);
    } else if (bx < 1024 + 4096) {
        const int z = bx - 1024;                // 0..4095, 4096 float4 each
        const float4 zero4 = make_float4(0.f, 0.f, 0.f, 0.f);
        const int base = z * 4096 + t;
        #pragma unroll
        for (int i = 0; i < 32; i++) attn4[base + i * 128] = zero4;
    } else {
        // prep: batch arrays -> int32, ranges, tile worklist.
        const int is32p = (bpraw[NP - 1] != 0);
        const int is32l = (blraw[NL - 1] != 0);
        if (t < NB) { g_pstart[t] = 0; g_pend[t] = 0; g_lstart[t] = 0; g_lend[t] = 0; }
        for (int i = t; i < NP; i += 128) g_bp[i] = is32p ? bpraw[i] : bpraw[2 * i];
        for (int i = t; i < NL; i += 128) g_bl[i] = is32l ? blraw[i] : blraw[2 * i];
        __syncthreads();
        for (int i = t; i < NP; i += 128) {
            const int b = g_bp[i];
            if (i == 0 || g_bp[i - 1] != b) g_pstart[b] = i;
            if (i == NP - 1 || g_bp[i + 1] != b) g_pend[b] = i + 1;
        }
        for (int i = t; i < NL; i += 128) {
            const int b = g_bl[i];
            if (i == 0 || g_bl[i - 1] != b) g_lstart[b] = i;
            if (i == NL - 1 || g_bl[i + 1] != b) g_lend[b] = i + 1;
        }
        __syncthreads();
        if (t == 0) {
            int idx = 0;
            for (int b = 0; b < NB; b++)
                for (int r = g_pstart[b]; r < g_pend[b]; r += 64) {
                    g_tile_b[idx] = b; g_tile_r[idx] = r; idx++;
                }
            for (; idx < MAXT; idx++) g_tile_b[idx] = -1;
        }
    }
}

// Standalone GEMM wrapper (output projection).
__global__ void __launch_bounds__(128) gemm_tf32(const float* __restrict__ X,
                                                 const float* __restrict__ W,
                                                 const float* __restrict__ bias,
                                                 const float* __restrict__ res,
                                                 float* __restrict__ Y)
{
    gemm_tile(X, W, bias, res, Y, blockIdx.y * 64, blockIdx.x * 64);
}

// ---------------------------------------------------------------------------
// Fused attention: per (row-tile 64, head), 256 threads.
// Phase A: S = (Q*0.125).K^T (cp.async double-buffered), raw scores -> attn,
//          then in-kernel softmax over [l0, l1) (warp per 8 rows, single exp).
// Phase B: C = P.V — P re-read from attn (same-SM L1/L2 hot) into the K
//          buffers (identical layout), V cp.async-staged; writes scrambled
//          ctx layout (h*NP+p)*64 + d.
// ---------------------------------------------------------------------------
#define SPAD 68
#define VPAD 72

__global__ void __launch_bounds__(256) attn_fused(const float* __restrict__ Q,
                                                  const float* __restrict__ Km,
                                                  const float* __restrict__ Vm,
                                                  float* __restrict__ attn,
                                                  float* __restrict__ ctx)
{
    const int b = g_tile_b[blockIdx.x];
    if (b < 0) return;
    const int r0 = g_tile_r[blockIdx.x];
    const int nr = min(64, g_pend[b] - r0);
    const int l0 = g_lstart[b], l1 = g_lend[b];
    const int h  = blockIdx.y;
    const int al0 = l0 & ~63;
    const int nch = (l1 - al0 + 63) >> 6;

    __shared__ __align__(16) float Qs[64 * SPAD];        // [row][k], prescaled
    __shared__ __align__(16) float Ks[2][64 * SPAD];     // K chunks; reused as P
    __shared__ __align__(16) float Vs[2][64 * VPAD];     // [l][d]

    const int t = threadIdx.x;
    const int lane = t & 31, w = t >> 5;
    const int wm = w >> 2, wn = w & 3;
    const int m0 = wm * 32, n0 = wn * 16;
    const int gid = lane >> 2, q4 = lane & 3;

    // ---------------- Phase A: scores + softmax ----------------
    auto stageK = [&](int buf, int lc) {
        #pragma unroll
        for (int j = 0; j < 4; j++) {
            const int i = t + j * 256;               // 0..1023
            const int col = i >> 4, q = (i & 15) * 4;
            cp16(&Ks[buf][col * SPAD + q], Km + (size_t)(lc + col) * DM + h * 64 + q);
        }
    };

    stageK(0, al0);
    CP_COMMIT();

    #pragma unroll
    for (int i = t; i < 1024; i += 256) {
        const int row = i >> 4, q = (i & 15) * 4;
        float4 v = make_float4(0.f, 0.f, 0.f, 0.f);
        if (row < nr)
            v = *reinterpret_cast<const float4*>(Q + (size_t)(r0 + row) * DM + h * 64 + q);
        v.x = to_tf32(v.x * 0.125f); v.y = to_tf32(v.y * 0.125f);
        v.z = to_tf32(v.z * 0.125f); v.w = to_tf32(v.w * 0.125f);
        *reinterpret_cast<float4*>(&Qs[row * SPAD + q]) = v;
    }

    for (int ch = 0; ch < nch; ch++) {
        const int lc = al0 + ch * 64;
        const int buf = ch & 1;
        if (ch + 1 < nch) {
            stageK(buf ^ 1, lc + 64);
            CP_COMMIT();
            CP_WAIT(1);
        } else {
            CP_WAIT(0);
        }
        __syncthreads();

        float d[2][2][4] = {};
        #pragma unroll
        for (int kk = 0; kk < 64; kk += 8) {
            uint32_t a[2][4], bb[2][2];
            #pragma unroll
            for (int mt = 0; mt < 2; mt++) {
                const int rb = m0 + mt * 16 + gid;
                a[mt][0] = __float_as_uint(Qs[rb * SPAD + kk + q4]);
                a[mt][1] = __float_as_uint(Qs[(rb + 8) * SPAD + kk + q4]);
                a[mt][2] = __float_as_uint(Qs[rb * SPAD + kk + q4 + 4]);
                a[mt][3] = __float_as_uint(Qs[(rb + 8) * SPAD + kk + q4 + 4]);
            }
            #pragma unroll
            for (int nt = 0; nt < 2; nt++) {
                const int nb = n0 + nt * 8 + gid;
                bb[nt][0] = __float_as_uint(Ks[buf][nb * SPAD + kk + q4]);
                bb[nt][1] = __float_as_uint(Ks[buf][nb * SPAD + kk + q4 + 4]);
            }
            #pragma unroll
            for (int mt = 0; mt < 2; mt++)
                #pragma unroll
                for (int nt = 0; nt < 2; nt++)
                    MMA_TF32(d[mt][nt], a[mt], bb[nt]);
        }

        #pragma unroll
        for (int mt = 0; mt < 2; mt++) {
            #pragma unroll
            for (int nt = 0; nt < 2; nt++) {
                const int rr = m0 + mt * 16 + gid;
                const int c  = lc + n0 + nt * 8 + q4 * 2;
                float* a0 = attn + ((size_t)h * NP + (r0 + rr)) * NL;
                float* a1 = a0 + 8 * NL;
                if (rr < nr) {
                    if (c >= l0 && c < l1)         a0[c]     = d[mt][nt][0];
                    if (c + 1 >= l0 && c + 1 < l1) a0[c + 1] = d[mt][nt][1];
                }
                if (rr + 8 < nr) {
                    if (c >= l0 && c < l1)         a1[c]     = d[mt][nt][2];
                    if (c + 1 >= l0 && c + 1 < l1) a1[c + 1] = d[mt][nt][3];
                }
            }
        }
        __syncthreads();
    }

    // Softmax over [l0, l1) per row (raw scores L2/L1-hot).
    #pragma unroll
    for (int rr8 = 0; rr8 < 8; rr8++) {
        const int row = w * 8 + rr8;
        if (row >= nr) continue;
        float* arow = attn + ((size_t)h * NP + (r0 + row)) * NL;

        float mx = -1e30f;
        for (int l = l0 + lane; l < l1; l += 32) mx = fmaxf(mx, arow[l]);
        #pragma unroll
        for (int o = 16; o; o >>= 1) mx = fmaxf(mx, __shfl_xor_sync(0xffffffffu, mx, o));

        float sum = 0.f;
        for (int l = l0 + lane; l < l1; l += 32) {
            const float e = __expf(arow[l] - mx);
            arow[l] = e;
            sum += e;
        }
        #pragma unroll
        for (int o = 16; o; o >>= 1) sum += __shfl_xor_sync(0xffffffffu, sum, o);
        const float inv = 1.f / sum;

        for (int l = l0 + lane; l < l1; l += 32) arow[l] *= inv;
    }
    __syncthreads();   // all rows normalized before phase B reads them

    // ---------------- Phase B: context ----------------
    auto stagePV = [&](int buf, int lc) {
        #pragma unroll
        for (int j = 0; j < 4; j++) {
            const int i = t + j * 256;
            const int row = i >> 4, q = (i & 15) * 4;
            if (row < nr)
                cp16(&Ks[buf][row * SPAD + q],
                     attn + ((size_t)h * NP + (r0 + row)) * NL + lc + q);
        }
        #pragma unroll
        for (int j = 0; j < 4; j++) {
            const int i = t + j * 256;
            const int l = i >> 4, q = (i & 15) * 4;
            cp16(&Vs[buf][l * VPAD + q], Vm + (size_t)(lc + l) * DM + h * 64 + q);
        }
    };

    float d[2][2][4] = {};

    stagePV(0, al0);
    CP_COMMIT();

    for (int ch = 0; ch < nch; ch++) {
        const int buf = ch & 1;
        if (ch + 1 < nch) {
            stagePV(buf ^ 1, al0 + (ch + 1) * 64);
            CP_COMMIT();
            CP_WAIT(1);
        } else {
            CP_WAIT(0);
        }
        __syncthreads();

        #pragma unroll
        for (int kk = 0; kk < 64; kk += 8) {
            uint32_t a[2][4], bb[2][2];
            #pragma unroll
            for (int mt = 0; mt < 2; mt++) {
                const int rb = m0 + mt * 16 + gid;
                a[mt][0] = __float_as_uint(Ks[buf][rb * SPAD + kk + q4]);
                a[mt][1] = __float_as_uint(Ks[buf][(rb + 8) * SPAD + kk + q4]);
                a[mt][2] = __float_as_uint(Ks[buf][rb * SPAD + kk + q4 + 4]);
                a[mt][3] = __float_as_uint(Ks[buf][(rb + 8) * SPAD + kk + q4 + 4]);
            }
            #pragma unroll
            for (int nt = 0; nt < 2; nt++) {
                const int nb = n0 + nt * 8 + gid;   // d-column
                bb[nt][0] = __float_as_uint(Vs[buf][(kk + q4) * VPAD + nb]);
                bb[nt][1] = __float_as_uint(Vs[buf][(kk + q4 + 4) * VPAD + nb]);
            }
            #pragma unroll
            for (int mt = 0; mt < 2; mt++)
                #pragma unroll
                for (int nt = 0; nt < 2; nt++)
                    MMA_TF32(d[mt][nt], a[mt], bb[nt]);
        }
        __syncthreads();
    }

    #pragma unroll
    for (int mt = 0; mt < 2; mt++) {
        #pragma unroll
        for (int nt = 0; nt < 2; nt++) {
            const int rr = m0 + mt * 16 + gid;
            const int c  = n0 + nt * 8 + q4 * 2;
            if (rr < nr) {
                float* o = ctx + ((size_t)h * NP + (r0 + rr)) * 64;
                o[c] = d[mt][nt][0]; o[c + 1] = d[mt][nt][1];
            }
            if (rr + 8 < nr) {
                float* o = ctx + ((size_t)h * NP + (r0 + rr + 8)) * 64;
                o[c] = d[mt][nt][2]; o[c + 1] = d[mt][nt][3];
            }
        }
    }
}

// ---------------------------------------------------------------------------
// LayerNorm: warp per row over 512 features.
// ---------------------------------------------------------------------------
__global__ void ln_kernel(const float* __restrict__ X,
                          const float* __restrict__ gamma,
                          const float* __restrict__ beta,
                          float* __restrict__ out)
{
    const int row  = blockIdx.x * 8 + (threadIdx.x >> 5);
    const int lane = threadIdx.x & 31;
    const float* xr = X + (size_t)row * DM;

    float v[16];
    float s = 0.f;
    #pragma unroll
    for (int i = 0; i < 16; i++) { v[i] = xr[lane + i * 32]; s += v[i]; }
    #pragma unroll
    for (int o = 16; o; o >>= 1) s += __shfl_xor_sync(0xffffffffu, s, o);
    const float mu = s * (1.f / 512.f);

    float q = 0.f;
    #pragma unroll
    for (int i = 0; i < 16; i++) { const float d = v[i] - mu; q += d * d; }
    #pragma unroll
    for (int o = 16; o; o >>= 1) q += __shfl_xor_sync(0xffffffffu, q, o);
    const float rstd = rsqrtf(q * (1.f / 512.f) + 1e-5f);

    #pragma unroll
    for (int i = 0; i < 16; i++) {
        const int c = lane + i * 32;
        out[(size_t)row * DM + c] = (v[i] - mu) * rstd * gamma[c] + beta[c];
    }
}

// ---------------------------------------------------------------------------
extern "C" void kernel_launch(void* const* d_in, const int* in_sizes, int n_in,
                              void* d_out, int out_size)
{
    const float* protein = (const float*)d_in[0];
    const float* ligand  = (const float*)d_in[1];
    const int* bp_raw    = (const int*)d_in[2];
    const int* bl_raw    = (const int*)d_in[3];
    const float* Wq = (const float*)d_in[4];
    const float* bq = (const float*)d_in[5];
    const float* Wk = (const float*)d_in[6];
    const float* bk = (const float*)d_in[7];
    const float* Wv = (const float*)d_in[8];
    const float* bv = (const float*)d_in[9];
    const float* Wo = (const float*)d_in[10];
    const float* bo = (const float*)d_in[11];
    const float* gamma = (const float*)d_in[12];
    const float* beta  = (const float*)d_in[13];

    float* out  = (float*)d_out;                      // [4096, 512]
    float* attn = out + (size_t)NP * DM;              // [1, 8, 4096, 2048]

    float *Qp, *Kp, *Vp, *Cp, *Tp;
    cudaGetSymbolAddress((void**)&Qp, g_Q);
    cudaGetSymbolAddress((void**)&Kp, g_K);
    cudaGetSymbolAddress((void**)&Vp, g_V);
    cudaGetSymbolAddress((void**)&Cp, g_ctx);
    cudaGetSymbolAddress((void**)&Tp, g_tmp);

    // Phase 1: Q/K/V projections + attn zero-fill + batch prep, one launch
    p1_kernel<<<1024 + 4096 + 1, 128>>>(protein, ligand, bp_raw, bl_raw,
                                        Wq, bq, Wk, bk, Wv, bv,
                                        Qp, Kp, Vp, (float4*)attn);

    // Fused scores + softmax + context (tensor cores throughout)
    attn_fused<<<dim3(MAXT, NH), 256>>>(Qp, Kp, Vp, attn, Cp);

    // Output projection + residual, then LayerNorm
    gemm_tf32<<<dim3(DM / 64, NP / 64), 128>>>(Cp, Wo, bo, protein, Tp);
    ln_kernel<<<NP / 8, 256>>>(Tp, gamma, beta, out);
}

// round 15
// speedup vs baseline: 1.1277x; 1.1277x over previous
#include <cuda_runtime.h>
#include <cuda_bf16.h>
#include <cstdint>

#define NP 4096
#define NL 2048
#define DM 512
#define NH 8
#define DK 64
#define NB 16
#define MAXT 80   // max row tiles: 4096/64 + 16

// Scratch (allocation-free rule: __device__ globals)
__device__ float g_Q[NP * DM];
__device__ float g_K[NL * DM];
__device__ float g_V[NL * DM];
__device__ float g_ctx[NP * DM];
__device__ float g_tmp[NP * DM];
__device__ int   g_bp[NP];
__device__ int   g_bl[NL];
__device__ int   g_pstart[NB], g_pend[NB];
__device__ int   g_lstart[NB], g_lend[NB];
__device__ int   g_tile_b[MAXT], g_tile_r[MAXT];

__device__ __forceinline__ float to_tf32(float x) {
    float y;
    asm("cvt.rna.tf32.f32 %0, %1;" : "=f"(y) : "f"(x));
    return y;
}

#define MMA_TF32(d, a, b) \
    asm volatile("mma.sync.aligned.m16n8k8.row.col.f32.tf32.tf32.f32 " \
        "{%0,%1,%2,%3}, {%4,%5,%6,%7}, {%8,%9}, {%0,%1,%2,%3};" \
        : "+f"((d)[0]), "+f"((d)[1]), "+f"((d)[2]), "+f"((d)[3]) \
        : "r"((a)[0]), "r"((a)[1]), "r"((a)[2]), "r"((a)[3]), \
          "r"((b)[0]), "r"((b)[1]))

__device__ __forceinline__ void cp16(void* sdst, const void* gsrc) {
    uint32_t s = (uint32_t)__cvta_generic_to_shared(sdst);
    asm volatile("cp.async.ca.shared.global [%0], [%1], 16;" :: "r"(s), "l"(gsrc) : "memory");
}
#define CP_COMMIT() asm volatile("cp.async.commit_group;" ::: "memory")
#define CP_WAIT(n)  asm volatile("cp.async.wait_group %0;" :: "n"(n) : "memory")

// ---------------------------------------------------------------------------
// tf32 mma GEMM tile, cp.async 3-stage pipelined.
// Y[64,128] = X[64,K] W[128,K]^T + bias (+res). 8 warps (2x4), warp 32x32.
// 3 stages keep a full chunk of latency slack against L2 (~250cy).
// ---------------------------------------------------------------------------
#define GK   16
#define GPAD 20
#define NSTG 3

__device__ __forceinline__ void gemm_tile(const float* __restrict__ X,
                                          const float* __restrict__ W,
                                          const float* __restrict__ bias,
                                          const float* __restrict__ res,
                                          float* __restrict__ Y,
                                          int row0, int col0)
{
    __shared__ __align__(16) float Xs[NSTG][64 * GPAD];
    __shared__ __align__(16) float Ws[NSTG][128 * GPAD];

    const int t = threadIdx.x;
    const int lane = t & 31, w = t >> 5;
    const int wm = w >> 2, wn = w & 3;          // 2 x 4 warp grid
    const int m0 = wm * 32, n0 = wn * 32;       // warp tile 32x32
    const int gid = lane >> 2, q4 = lane & 3;

    float d[2][4][4] = {};

    // stage chunk into buf: X 64x16 = 256 float4, W 128x16 = 512 float4
    auto stage = [&](int buf, int k0) {
        #pragma unroll
        for (int j = 0; j < 3; j++) {
            const int f = t + j * 256;           // 0..767
            if (f < 256) {
                const int r = f >> 2, q = (f & 3) * 4;
                cp16(&Xs[buf][r * GPAD + q], X + (size_t)(row0 + r) * DM + k0 + q);
            } else {
                const int g = f - 256;
                const int r = g >> 2, q = (g & 3) * 4;
                cp16(&Ws[buf][r * GPAD + q], W + (size_t)(col0 + r) * DM + k0 + q);
            }
        }
    };

    const int NCH = DM / GK;   // 32 chunks
    stage(0, 0); CP_COMMIT();
    stage(1, GK); CP_COMMIT();

    for (int kc = 0; kc < NCH; kc++) {
        const int buf = kc % NSTG;
        if (kc + 2 < NCH) {
            stage((kc + 2) % NSTG, (kc + 2) * GK);
            CP_COMMIT();
            CP_WAIT(2);            // chunk kc's group complete
        } else if (kc + 1 < NCH) {
            CP_WAIT(1);
        } else {
            CP_WAIT(0);
        }
        __syncthreads();

        #pragma unroll
        for (int kk = 0; kk < GK; kk += 8) {
            uint32_t a[2][4], b[4][2];
            #pragma unroll
            for (int mt = 0; mt < 2; mt++) {
                const int rb = m0 + mt * 16 + gid;
                a[mt][0] = __float_as_uint(Xs[buf][rb * GPAD + kk + q4]);
                a[mt][1] = __float_as_uint(Xs[buf][(rb + 8) * GPAD + kk + q4]);
                a[mt][2] = __float_as_uint(Xs[buf][rb * GPAD + kk + q4 + 4]);
                a[mt][3] = __float_as_uint(Xs[buf][(rb + 8) * GPAD + kk + q4 + 4]);
            }
            #pragma unroll
            for (int nt = 0; nt < 4; nt++) {
                const int nb = n0 + nt * 8 + gid;
                b[nt][0] = __float_as_uint(Ws[buf][nb * GPAD + kk + q4]);
                b[nt][1] = __float_as_uint(Ws[buf][nb * GPAD + kk + q4 + 4]);
            }
            #pragma unroll
            for (int mt = 0; mt < 2; mt++)
                #pragma unroll
                for (int nt = 0; nt < 4; nt++)
                    MMA_TF32(d[mt][nt], a[mt], b[nt]);
        }
        __syncthreads();
    }

    #pragma unroll
    for (int mt = 0; mt < 2; mt++) {
        #pragma unroll
        for (int nt = 0; nt < 4; nt++) {
            const int r1 = row0 + m0 + mt * 16 + gid;
            const int c  = col0 + n0 + nt * 8 + q4 * 2;
            const float b0 = bias[c], b1 = bias[c + 1];
            float2 o0 = make_float2(d[mt][nt][0] + b0, d[mt][nt][1] + b1);
            float2 o1 = make_float2(d[mt][nt][2] + b0, d[mt][nt][3] + b1);
            if (res) {
                const float2 r0v = *reinterpret_cast<const float2*>(res + (size_t)r1 * DM + c);
                const float2 r1v = *reinterpret_cast<const float2*>(res + (size_t)(r1 + 8) * DM + c);
                o0.x += r0v.x; o0.y += r0v.y;
                o1.x += r1v.x; o1.y += r1v.y;
            }
            *reinterpret_cast<float2*>(Y + (size_t)r1 * DM + c) = o0;
            *reinterpret_cast<float2*>(Y + (size_t)(r1 + 8) * DM + c) = o1;
        }
    }
}

// ---------------------------------------------------------------------------
// Phase 1 fused kernel:
//   CTAs [0,512)        : Q/K/V projections (64x128 tiles; Q:256, K:128, V:128)
//   CTAs [512, 512+4096): zero-fill of attn output (DRAM-bound)
//   CTA  4608           : batch prep (dtype normalize, ranges, tile worklist)
// ---------------------------------------------------------------------------
__global__ void __launch_bounds__(256) p1_kernel(
    const float* __restrict__ protein, const float* __restrict__ ligand,
    const int* __restrict__ bpraw, const int* __restrict__ blraw,
    const float* __restrict__ Wq, const float* __restrict__ bq,
    const float* __restrict__ Wk, const float* __restrict__ bk,
    const float* __restrict__ Wv, const float* __restrict__ bv,
    float* __restrict__ Qp, float* __restrict__ Kp, float* __restrict__ Vp,
    float4* __restrict__ attn4)
{
    const int bx = blockIdx.x;
    const int t = threadIdx.x;
    if (bx < 512) {
        const float *X, *W, *bias; float* Y; int lb;
        if (bx < 256)      { X = protein; W = Wq; bias = bq; Y = Qp; lb = bx; }
        else if (bx < 384) { X = ligand;  W = Wk; bias = bk; Y = Kp; lb = bx - 256; }
        else               { X = ligand;  W = Wv; bias = bv; Y = Vp; lb = bx - 384; }
        gemm_tile(X, W, bias, nullptr, Y, (lb >> 2) * 64, (lb & 3) * 128);
    } else if (bx < 512 + 4096) {
        const int z = bx - 512;                 // 0..4095, 4096 float4 each
        const float4 zero4 = make_float4(0.f, 0.f, 0.f, 0.f);
        const int base = z * 4096 + t;
        #pragma unroll
        for (int i = 0; i < 16; i++) attn4[base + i * 256] = zero4;
    } else {
        // prep: batch arrays -> int32, ranges, tile worklist.
        const int is32p = (bpraw[NP - 1] != 0);
        const int is32l = (blraw[NL - 1] != 0);
        if (t < NB) { g_pstart[t] = 0; g_pend[t] = 0; g_lstart[t] = 0; g_lend[t] = 0; }
        for (int i = t; i < NP; i += 256) g_bp[i] = is32p ? bpraw[i] : bpraw[2 * i];
        for (int i = t; i < NL; i += 256) g_bl[i] = is32l ? blraw[i] : blraw[2 * i];
        __syncthreads();
        for (int i = t; i < NP; i += 256) {
            const int b = g_bp[i];
            if (i == 0 || g_bp[i - 1] != b) g_pstart[b] = i;
            if (i == NP - 1 || g_bp[i + 1] != b) g_pend[b] = i + 1;
        }
        for (int i = t; i < NL; i += 256) {
            const int b = g_bl[i];
            if (i == 0 || g_bl[i - 1] != b) g_lstart[b] = i;
            if (i == NL - 1 || g_bl[i + 1] != b) g_lend[b] = i + 1;
        }
        __syncthreads();
        if (t == 0) {
            int idx = 0;
            for (int b = 0; b < NB; b++)
                for (int r = g_pstart[b]; r < g_pend[b]; r += 64) {
                    g_tile_b[idx] = b; g_tile_r[idx] = r; idx++;
                }
            for (; idx < MAXT; idx++) g_tile_b[idx] = -1;
        }
    }
}

// Standalone GEMM wrapper (output projection).
__global__ void __launch_bounds__(256) gemm_tf32(const float* __restrict__ X,
                                                 const float* __restrict__ W,
                                                 const float* __restrict__ bias,
                                                 const float* __restrict__ res,
                                                 float* __restrict__ Y)
{
    gemm_tile(X, W, bias, res, Y, blockIdx.y * 64, blockIdx.x * 128);
}

// ---------------------------------------------------------------------------
// Scores + softmax fused: per (row-tile 64, head).
// K chunks start at l0 & ~63 (16B-aligned cp.async sources); epilogue writes
// only columns in [l0, l1) — everything outside is exactly 0 (zero-fill).
// cp.async double-buffered K staging overlapped with MMA.
// ---------------------------------------------------------------------------
#define SPAD 68

__global__ void __launch_bounds__(256) score_sm(const float* __restrict__ Q,
                                                const float* __restrict__ Km,
                                                float* __restrict__ attn)
{
    const int b = g_tile_b[blockIdx.x];
    if (b < 0) return;
    const int r0 = g_tile_r[blockIdx.x];
    const int nr = min(64, g_pend[b] - r0);
    const int l0 = g_lstart[b], l1 = g_lend[b];
    const int h  = blockIdx.y;
    const int al0 = l0 & ~63;
    const int nch = (l1 - al0 + 63) >> 6;

    __shared__ __align__(16) float Qs[64 * SPAD];        // [row][k], prescaled
    __shared__ __align__(16) float Ks[2][64 * SPAD];     // [key][k] double buf

    const int t = threadIdx.x;
    const int lane = t & 31, w = t >> 5;
    const int wm = w >> 2, wn = w & 3;
    const int m0 = wm * 32, n0 = wn * 16;
    const int gid = lane >> 2, q4 = lane & 3;

    auto stageK = [&](int buf, int lc) {
        #pragma unroll
        for (int j = 0; j < 4; j++) {
            const int i = t + j * 256;               // 0..1023
            const int col = i >> 4, q = (i & 15) * 4;
            cp16(&Ks[buf][col * SPAD + q], Km + (size_t)(lc + col) * DM + h * 64 + q);
        }
    };

    stageK(0, al0);
    CP_COMMIT();

    // Q staging (scaled, tf32-rounded) overlaps with first K chunk in flight
    #pragma unroll
    for (int i = t; i < 1024; i += 256) {
        const int row = i >> 4, q = (i & 15) * 4;
        float4 v = make_float4(0.f, 0.f, 0.f, 0.f);
        if (row < nr)
            v = *reinterpret_cast<const float4*>(Q + (size_t)(r0 + row) * DM + h * 64 + q);
        v.x = to_tf32(v.x * 0.125f); v.y = to_tf32(v.y * 0.125f);
        v.z = to_tf32(v.z * 0.125f); v.w = to_tf32(v.w * 0.125f);
        *reinterpret_cast<float4*>(&Qs[row * SPAD + q]) = v;
    }

    for (int ch = 0; ch < nch; ch++) {
        const int lc = al0 + ch * 64;
        const int buf = ch & 1;
        if (ch + 1 < nch) {
            stageK(buf ^ 1, lc + 64);
            CP_COMMIT();
            CP_WAIT(1);
        } else {
            CP_WAIT(0);
        }
        __syncthreads();

        float d[2][2][4] = {};
        #pragma unroll
        for (int kk = 0; kk < 64; kk += 8) {
            uint32_t a[2][4], bb[2][2];
            #pragma unroll
            for (int mt = 0; mt < 2; mt++) {
                const int rb = m0 + mt * 16 + gid;
                a[mt][0] = __float_as_uint(Qs[rb * SPAD + kk + q4]);
                a[mt][1] = __float_as_uint(Qs[(rb + 8) * SPAD + kk + q4]);
                a[mt][2] = __float_as_uint(Qs[rb * SPAD + kk + q4 + 4]);
                a[mt][3] = __float_as_uint(Qs[(rb + 8) * SPAD + kk + q4 + 4]);
            }
            #pragma unroll
            for (int nt = 0; nt < 2; nt++) {
                const int nb = n0 + nt * 8 + gid;
                bb[nt][0] = __float_as_uint(Ks[buf][nb * SPAD + kk + q4]);
                bb[nt][1] = __float_as_uint(Ks[buf][nb * SPAD + kk + q4 + 4]);
            }
            #pragma unroll
            for (int mt = 0; mt < 2; mt++)
                #pragma unroll
                for (int nt = 0; nt < 2; nt++)
                    MMA_TF32(d[mt][nt], a[mt], bb[nt]);
        }

        #pragma unroll
        for (int mt = 0; mt < 2; mt++) {
            #pragma unroll
            for (int nt = 0; nt < 2; nt++) {
                const int rr = m0 + mt * 16 + gid;
                const int c  = lc + n0 + nt * 8 + q4 * 2;
                float* a0 = attn + ((size_t)h * NP + (r0 + rr)) * NL;
                float* a1 = a0 + 8 * NL;
                if (rr < nr) {
                    if (c >= l0 && c < l1)         a0[c]     = d[mt][nt][0];
                    if (c + 1 >= l0 && c + 1 < l1) a0[c + 1] = d[mt][nt][1];
                }
                if (rr + 8 < nr) {
                    if (c >= l0 && c < l1)         a1[c]     = d[mt][nt][2];
                    if (c + 1 >= l0 && c + 1 < l1) a1[c + 1] = d[mt][nt][3];
                }
            }
        }
        __syncthreads();
    }

    // Softmax over [l0, l1) per row; raw scores are L2-hot.
    #pragma unroll
    for (int rr8 = 0; rr8 < 8; rr8++) {
        const int row = w * 8 + rr8;
        if (row >= nr) continue;
        float* arow = attn + ((size_t)h * NP + (r0 + row)) * NL;

        float mx = -1e30f;
        for (int l = l0 + lane; l < l1; l += 32) mx = fmaxf(mx, arow[l]);
        #pragma unroll
        for (int o = 16; o; o >>= 1) mx = fmaxf(mx, __shfl_xor_sync(0xffffffffu, mx, o));

        float sum = 0.f;
        for (int l = l0 + lane; l < l1; l += 32) {
            const float e = __expf(arow[l] - mx);
            arow[l] = e;
            sum += e;
        }
        #pragma unroll
        for (int o = 16; o; o >>= 1) sum += __shfl_xor_sync(0xffffffffu, sum, o);
        const float inv = 1.f / sum;

        for (int l = l0 + lane; l < l1; l += 32) arow[l] *= inv;
    }
}

// ---------------------------------------------------------------------------
// Context via tf32 mma, cp.async double-buffered P and V staging.
// Chunks aligned to l0 & ~63: P columns outside [l0,l1) are exactly 0 in attn
// (zero-fill + guarded score writes). P rows >= nr left unstaged (garbage
// reaches only discarded D rows). Writes scrambled layout (h*NP+p)*64 + d.
// ---------------------------------------------------------------------------
#define VPAD 72

__global__ void __launch_bounds__(256) ctx_mma(const float* __restrict__ attn,
                                               const float* __restrict__ Vm,
                                               float* __restrict__ ctx)
{
    const int b = g_tile_b[blockIdx.x];
    if (b < 0) return;
    const int r0 = g_tile_r[blockIdx.x];
    const int nr = min(64, g_pend[b] - r0);
    const int l0 = g_lstart[b], l1 = g_lend[b];
    const int h  = blockIdx.y;
    const int al0 = l0 & ~63;
    const int nch = (l1 - al0 + 63) >> 6;

    __shared__ __align__(16) float Ps[2][64 * SPAD];   // [row][l]
    __shared__ __align__(16) float Vs[2][64 * VPAD];   // [l][d]

    const int t = threadIdx.x;
    const int lane = t & 31, w = t >> 5;
    const int wm = w >> 2, wn = w & 3;
    const int m0 = wm * 32, n0 = wn * 16;
    const int gid = lane >> 2, q4 = lane & 3;

    auto stagePV = [&](int buf, int lc) {
        #pragma unroll
        for (int j = 0; j < 4; j++) {
            const int i = t + j * 256;
            const int row = i >> 4, q = (i & 15) * 4;
            if (row < nr)
                cp16(&Ps[buf][row * SPAD + q],
                     attn + ((size_t)h * NP + (r0 + row)) * NL + lc + q);
        }
        #pragma unroll
        for (int j = 0; j < 4; j++) {
            const int i = t + j * 256;
            const int l = i >> 4, q = (i & 15) * 4;
            cp16(&Vs[buf][l * VPAD + q], Vm + (size_t)(lc + l) * DM + h * 64 + q);
        }
    };

    float d[2][2][4] = {};

    stagePV(0, al0);
    CP_COMMIT();

    for (int ch = 0; ch < nch; ch++) {
        const int buf = ch & 1;
        if (ch + 1 < nch) {
            stagePV(buf ^ 1, al0 + (ch + 1) * 64);
            CP_COMMIT();
            CP_WAIT(1);
        } else {
            CP_WAIT(0);
        }
        __syncthreads();

        #pragma unroll
        for (int kk = 0; kk < 64; kk += 8) {
            uint32_t a[2][4], bb[2][2];
            #pragma unroll
            for (int mt = 0; mt < 2; mt++) {
                const int rb = m0 + mt * 16 + gid;
                a[mt][0] = __float_as_uint(Ps[buf][rb * SPAD + kk + q4]);
                a[mt][1] = __float_as_uint(Ps[buf][(rb + 8) * SPAD + kk + q4]);
                a[mt][2] = __float_as_uint(Ps[buf][rb * SPAD + kk + q4 + 4]);
                a[mt][3] = __float_as_uint(Ps[buf][(rb + 8) * SPAD + kk + q4 + 4]);
            }
            #pragma unroll
            for (int nt = 0; nt < 2; nt++) {
                const int nb = n0 + nt * 8 + gid;   // d-column
                bb[nt][0] = __float_as_uint(Vs[buf][(kk + q4) * VPAD + nb]);
                bb[nt][1] = __float_as_uint(Vs[buf][(kk + q4 + 4) * VPAD + nb]);
            }
            #pragma unroll
            for (int mt = 0; mt < 2; mt++)
                #pragma unroll
                for (int nt = 0; nt < 2; nt++)
                    MMA_TF32(d[mt][nt], a[mt], bb[nt]);
        }
        __syncthreads();
    }

    #pragma unroll
    for (int mt = 0; mt < 2; mt++) {
        #pragma unroll
        for (int nt = 0; nt < 2; nt++) {
            const int rr = m0 + mt * 16 + gid;
            const int c  = n0 + nt * 8 + q4 * 2;
            if (rr < nr) {
                float* o = ctx + ((size_t)h * NP + (r0 + rr)) * 64;
                o[c] = d[mt][nt][0]; o[c + 1] = d[mt][nt][1];
            }
            if (rr + 8 < nr) {
                float* o = ctx + ((size_t)h * NP + (r0 + rr + 8)) * 64;
                o[c] = d[mt][nt][2]; o[c + 1] = d[mt][nt][3];
            }
        }
    }
}

// ---------------------------------------------------------------------------
// LayerNorm: warp per row over 512 features.
// ---------------------------------------------------------------------------
__global__ void ln_kernel(const float* __restrict__ X,
                          const float* __restrict__ gamma,
                          const float* __restrict__ beta,
                          float* __restrict__ out)
{
    const int row  = blockIdx.x * 8 + (threadIdx.x >> 5);
    const int lane = threadIdx.x & 31;
    const float* xr = X + (size_t)row * DM;

    float v[16];
    float s = 0.f;
    #pragma unroll
    for (int i = 0; i < 16; i++) { v[i] = xr[lane + i * 32]; s += v[i]; }
    #pragma unroll
    for (int o = 16; o; o >>= 1) s += __shfl_xor_sync(0xffffffffu, s, o);
    const float mu = s * (1.f / 512.f);

    float q = 0.f;
    #pragma unroll
    for (int i = 0; i < 16; i++) { const float d = v[i] - mu; q += d * d; }
    #pragma unroll
    for (int o = 16; o; o >>= 1) q += __shfl_xor_sync(0xffffffffu, q, o);
    const float rstd = rsqrtf(q * (1.f / 512.f) + 1e-5f);

    #pragma unroll
    for (int i = 0; i < 16; i++) {
        const int c = lane + i * 32;
        out[(size_t)row * DM + c] = (v[i] - mu) * rstd * gamma[c] + beta[c];
    }
}

// ---------------------------------------------------------------------------
extern "C" void kernel_launch(void* const* d_in, const int* in_sizes, int n_in,
                              void* d_out, int out_size)
{
    const float* protein = (const float*)d_in[0];
    const float* ligand  = (const float*)d_in[1];
    const int* bp_raw    = (const int*)d_in[2];
    const int* bl_raw    = (const int*)d_in[3];
    const float* Wq = (const float*)d_in[4];
    const float* bq = (const float*)d_in[5];
    const float* Wk = (const float*)d_in[6];
    const float* bk = (const float*)d_in[7];
    const float* Wv = (const float*)d_in[8];
    const float* bv = (const float*)d_in[9];
    const float* Wo = (const float*)d_in[10];
    const float* bo = (const float*)d_in[11];
    const float* gamma = (const float*)d_in[12];
    const float* beta  = (const float*)d_in[13];

    float* out  = (float*)d_out;                      // [4096, 512]
    float* attn = out + (size_t)NP * DM;              // [1, 8, 4096, 2048]

    float *Qp, *Kp, *Vp, *Cp, *Tp;
    cudaGetSymbolAddress((void**)&Qp, g_Q);
    cudaGetSymbolAddress((void**)&Kp, g_K);
    cudaGetSymbolAddress((void**)&Vp, g_V);
    cudaGetSymbolAddress((void**)&Cp, g_ctx);
    cudaGetSymbolAddress((void**)&Tp, g_tmp);

    // Phase 1: Q/K/V projections + attn zero-fill + batch prep, one launch
    p1_kernel<<<512 + 4096 + 1, 256>>>(protein, ligand, bp_raw, bl_raw,
                                       Wq, bq, Wk, bk, Wv, bv,
                                       Qp, Kp, Vp, (float4*)attn);

    // Scores + softmax fused, then context (tensor cores throughout)
    score_sm<<<dim3(MAXT, NH), 256>>>(Qp, Kp, attn);
    ctx_mma<<<dim3(MAXT, NH), 256>>>(attn, Vp, Cp);

    // Output projection + residual, then LayerNorm
    gemm_tf32<<<dim3(DM / 128, NP / 64), 256>>>(Cp, Wo, bo, protein, Tp);
    ln_kernel<<<NP / 8, 256>>>(Tp, gamma, beta, out);
}

// round 16
// speedup vs baseline: 1.2571x; 1.1147x over previous
#include <cuda_runtime.h>
#include <cuda_bf16.h>
#include <cstdint>

#define NP 4096
#define NL 2048
#define DM 512
#define NH 8
#define DK 64
#define NB 16
#define MAXT 80   // max row tiles: 4096/64 + 16

// Scratch (allocation-free rule: __device__ globals)
__device__ float g_Q[NP * DM];
__device__ float g_K[NL * DM];
__device__ float g_V[NL * DM];
__device__ float g_ctx[NP * DM];
__device__ float g_tmp[NP * DM];
__device__ int   g_bp[NP];
__device__ int   g_bl[NL];
__device__ int   g_pstart[NB], g_pend[NB];
__device__ int   g_lstart[NB], g_lend[NB];
__device__ int   g_tile_b[MAXT], g_tile_r[MAXT];

__device__ __forceinline__ float to_tf32(float x) {
    float y;
    asm("cvt.rna.tf32.f32 %0, %1;" : "=f"(y) : "f"(x));
    return y;
}

#define MMA_TF32(d, a, b) \
    asm volatile("mma.sync.aligned.m16n8k8.row.col.f32.tf32.tf32.f32 " \
        "{%0,%1,%2,%3}, {%4,%5,%6,%7}, {%8,%9}, {%0,%1,%2,%3};" \
        : "+f"((d)[0]), "+f"((d)[1]), "+f"((d)[2]), "+f"((d)[3]) \
        : "r"((a)[0]), "r"((a)[1]), "r"((a)[2]), "r"((a)[3]), \
          "r"((b)[0]), "r"((b)[1]))

__device__ __forceinline__ void cp16(void* sdst, const void* gsrc) {
    uint32_t s = (uint32_t)__cvta_generic_to_shared(sdst);
    asm volatile("cp.async.ca.shared.global [%0], [%1], 16;" :: "r"(s), "l"(gsrc) : "memory");
}
#define CP_COMMIT() asm volatile("cp.async.commit_group;" ::: "memory")
#define CP_WAIT(n)  asm volatile("cp.async.wait_group %0;" :: "n"(n) : "memory")

// ---------------------------------------------------------------------------
// tf32 mma GEMM tile, cp.async double-buffered, K-chunk 32 (16 chunks total:
// halves the per-chunk barrier/drain overhead vs GK=16).
// Y[128,128] = X[128,K] W[128,K]^T + bias (+res). 8 warps (2x4), warp 64x32.
// GPAD=36: proven conflict-free fragment pattern (R8/R12) and 16B-aligned
// staging (36 % 4 == 0).
// ---------------------------------------------------------------------------
#define GK   32
#define GPAD 36

__device__ __forceinline__ void gemm_tile(const float* __restrict__ X,
                                          const float* __restrict__ W,
                                          const float* __restrict__ bias,
                                          const float* __restrict__ res,
                                          float* __restrict__ Y,
                                          int row0, int col0)
{
    __shared__ __align__(16) float Xs[2][128 * GPAD];
    __shared__ __align__(16) float Ws[2][128 * GPAD];

    const int t = threadIdx.x;
    const int lane = t & 31, w = t >> 5;
    const int wm = w >> 2, wn = w & 3;          // 2 x 4 warp grid
    const int m0 = wm * 64, n0 = wn * 32;       // warp tile 64x32
    const int gid = lane >> 2, q4 = lane & 3;

    float d[4][4][4] = {};

    // stage chunk into buf: X and W each 128 rows x 8 float4 = 1024 float4
    auto stage = [&](int buf, int k0) {
        #pragma unroll
        for (int j = 0; j < 4; j++) {
            const int f = t + j * 256;           // 0..1023
            const int r = f >> 3, q = (f & 7) * 4;
            cp16(&Xs[buf][r * GPAD + q], X + (size_t)(row0 + r) * DM + k0 + q);
            cp16(&Ws[buf][r * GPAD + q], W + (size_t)(col0 + r) * DM + k0 + q);
        }
    };

    const int NCH = DM / GK;   // 16 chunks
    stage(0, 0);
    CP_COMMIT();

    for (int kc = 0; kc < NCH; kc++) {
        const int buf = kc & 1;
        if (kc + 1 < NCH) {
            stage(buf ^ 1, (kc + 1) * GK);
            CP_COMMIT();
            CP_WAIT(1);
        } else {
            CP_WAIT(0);
        }
        __syncthreads();

        #pragma unroll
        for (int kk = 0; kk < GK; kk += 8) {
            uint32_t a[4][4], b[4][2];
            #pragma unroll
            for (int mt = 0; mt < 4; mt++) {
                const int rb = m0 + mt * 16 + gid;
                a[mt][0] = __float_as_uint(Xs[buf][rb * GPAD + kk + q4]);
                a[mt][1] = __float_as_uint(Xs[buf][(rb + 8) * GPAD + kk + q4]);
                a[mt][2] = __float_as_uint(Xs[buf][rb * GPAD + kk + q4 + 4]);
                a[mt][3] = __float_as_uint(Xs[buf][(rb + 8) * GPAD + kk + q4 + 4]);
            }
            #pragma unroll
            for (int nt = 0; nt < 4; nt++) {
                const int nb = n0 + nt * 8 + gid;
                b[nt][0] = __float_as_uint(Ws[buf][nb * GPAD + kk + q4]);
                b[nt][1] = __float_as_uint(Ws[buf][nb * GPAD + kk + q4 + 4]);
            }
            #pragma unroll
            for (int mt = 0; mt < 4; mt++)
                #pragma unroll
                for (int nt = 0; nt < 4; nt++)
                    MMA_TF32(d[mt][nt], a[mt], b[nt]);
        }
        __syncthreads();
    }

    #pragma unroll
    for (int mt = 0; mt < 4; mt++) {
        #pragma unroll
        for (int nt = 0; nt < 4; nt++) {
            const int r1 = row0 + m0 + mt * 16 + gid;
            const int c  = col0 + n0 + nt * 8 + q4 * 2;
            const float b0 = bias[c], b1 = bias[c + 1];
            float2 o0 = make_float2(d[mt][nt][0] + b0, d[mt][nt][1] + b1);
            float2 o1 = make_float2(d[mt][nt][2] + b0, d[mt][nt][3] + b1);
            if (res) {
                const float2 r0v = *reinterpret_cast<const float2*>(res + (size_t)r1 * DM + c);
                const float2 r1v = *reinterpret_cast<const float2*>(res + (size_t)(r1 + 8) * DM + c);
                o0.x += r0v.x; o0.y += r0v.y;
                o1.x += r1v.x; o1.y += r1v.y;
            }
            *reinterpret_cast<float2*>(Y + (size_t)r1 * DM + c) = o0;
            *reinterpret_cast<float2*>(Y + (size_t)(r1 + 8) * DM + c) = o1;
        }
    }
}

// ---------------------------------------------------------------------------
// Phase 1 fused kernel:
//   CTAs [0,256)        : Q/K/V projections (128x128 tiles; Q:128, K:64, V:64)
//   CTAs [256, 256+4096): zero-fill of attn output (DRAM-bound)
//   CTA  4352           : batch prep (dtype normalize, ranges, tile worklist)
// ---------------------------------------------------------------------------
__global__ void __launch_bounds__(256) p1_kernel(
    const float* __restrict__ protein, const float* __restrict__ ligand,
    const int* __restrict__ bpraw, const int* __restrict__ blraw,
    const float* __restrict__ Wq, const float* __restrict__ bq,
    const float* __restrict__ Wk, const float* __restrict__ bk,
    const float* __restrict__ Wv, const float* __restrict__ bv,
    float* __restrict__ Qp, float* __restrict__ Kp, float* __restrict__ Vp,
    float4* __restrict__ attn4)
{
    const int bx = blockIdx.x;
    const int t = threadIdx.x;
    if (bx < 256) {
        const float *X, *W, *bias; float* Y; int lb;
        if (bx < 128)      { X = protein; W = Wq; bias = bq; Y = Qp; lb = bx; }
        else if (bx < 192) { X = ligand;  W = Wk; bias = bk; Y = Kp; lb = bx - 128; }
        else               { X = ligand;  W = Wv; bias = bv; Y = Vp; lb = bx - 192; }
        gemm_tile(X, W, bias, nullptr, Y, (lb >> 2) * 128, (lb & 3) * 128);
    } else if (bx < 256 + 4096) {
        const int z = bx - 256;                 // 0..4095, 4096 float4 each
        const float4 zero4 = make_float4(0.f, 0.f, 0.f, 0.f);
        const int base = z * 4096 + t;
        #pragma unroll
        for (int i = 0; i < 16; i++) attn4[base + i * 256] = zero4;
    } else {
        // prep: batch arrays -> int32, ranges, tile worklist.
        const int is32p = (bpraw[NP - 1] != 0);
        const int is32l = (blraw[NL - 1] != 0);
        if (t < NB) { g_pstart[t] = 0; g_pend[t] = 0; g_lstart[t] = 0; g_lend[t] = 0; }
        for (int i = t; i < NP; i += 256) g_bp[i] = is32p ? bpraw[i] : bpraw[2 * i];
        for (int i = t; i < NL; i += 256) g_bl[i] = is32l ? blraw[i] : blraw[2 * i];
        __syncthreads();
        for (int i = t; i < NP; i += 256) {
            const int b = g_bp[i];
            if (i == 0 || g_bp[i - 1] != b) g_pstart[b] = i;
            if (i == NP - 1 || g_bp[i + 1] != b) g_pend[b] = i + 1;
        }
        for (int i = t; i < NL; i += 256) {
            const int b = g_bl[i];
            if (i == 0 || g_bl[i - 1] != b) g_lstart[b] = i;
            if (i == NL - 1 || g_bl[i + 1] != b) g_lend[b] = i + 1;
        }
        __syncthreads();
        if (t == 0) {
            int idx = 0;
            for (int b = 0; b < NB; b++)
                for (int r = g_pstart[b]; r < g_pend[b]; r += 64) {
                    g_tile_b[idx] = b; g_tile_r[idx] = r; idx++;
                }
            for (; idx < MAXT; idx++) g_tile_b[idx] = -1;
        }
    }
}

// Standalone GEMM wrapper (output projection).
__global__ void __launch_bounds__(256) gemm_tf32(const float* __restrict__ X,
                                                 const float* __restrict__ W,
                                                 const float* __restrict__ bias,
                                                 const float* __restrict__ res,
                                                 float* __restrict__ Y)
{
    gemm_tile(X, W, bias, res, Y, blockIdx.y * 128, blockIdx.x * 128);
}

// ---------------------------------------------------------------------------
// Scores + softmax fused: per (row-tile 64, head).
// K chunks start at l0 & ~63 (16B-aligned cp.async sources); epilogue writes
// only columns in [l0, l1) — everything outside is exactly 0 (zero-fill).
// cp.async double-buffered K staging overlapped with MMA.
// ---------------------------------------------------------------------------
#define SPAD 68

__global__ void __launch_bounds__(256) score_sm(const float* __restrict__ Q,
                                                const float* __restrict__ Km,
                                                float* __restrict__ attn)
{
    const int b = g_tile_b[blockIdx.x];
    if (b < 0) return;
    const int r0 = g_tile_r[blockIdx.x];
    const int nr = min(64, g_pend[b] - r0);
    const int l0 = g_lstart[b], l1 = g_lend[b];
    const int h  = blockIdx.y;
    const int al0 = l0 & ~63;
    const int nch = (l1 - al0 + 63) >> 6;

    __shared__ __align__(16) float Qs[64 * SPAD];        // [row][k], prescaled
    __shared__ __align__(16) float Ks[2][64 * SPAD];     // [key][k] double buf

    const int t = threadIdx.x;
    const int lane = t & 31, w = t >> 5;
    const int wm = w >> 2, wn = w & 3;
    const int m0 = wm * 32, n0 = wn * 16;
    const int gid = lane >> 2, q4 = lane & 3;

    auto stageK = [&](int buf, int lc) {
        #pragma unroll
        for (int j = 0; j < 4; j++) {
            const int i = t + j * 256;               // 0..1023
            const int col = i >> 4, q = (i & 15) * 4;
            cp16(&Ks[buf][col * SPAD + q], Km + (size_t)(lc + col) * DM + h * 64 + q);
        }
    };

    stageK(0, al0);
    CP_COMMIT();

    // Q staging (scaled, tf32-rounded) overlaps with first K chunk in flight
    #pragma unroll
    for (int i = t; i < 1024; i += 256) {
        const int row = i >> 4, q = (i & 15) * 4;
        float4 v = make_float4(0.f, 0.f, 0.f, 0.f);
        if (row < nr)
            v = *reinterpret_cast<const float4*>(Q + (size_t)(r0 + row) * DM + h * 64 + q);
        v.x = to_tf32(v.x * 0.125f); v.y = to_tf32(v.y * 0.125f);
        v.z = to_tf32(v.z * 0.125f); v.w = to_tf32(v.w * 0.125f);
        *reinterpret_cast<float4*>(&Qs[row * SPAD + q]) = v;
    }

    for (int ch = 0; ch < nch; ch++) {
        const int lc = al0 + ch * 64;
        const int buf = ch & 1;
        if (ch + 1 < nch) {
            stageK(buf ^ 1, lc + 64);
            CP_COMMIT();
            CP_WAIT(1);
        } else {
            CP_WAIT(0);
        }
        __syncthreads();

        float d[2][2][4] = {};
        #pragma unroll
        for (int kk = 0; kk < 64; kk += 8) {
            uint32_t a[2][4], bb[2][2];
            #pragma unroll
            for (int mt = 0; mt < 2; mt++) {
                const int rb = m0 + mt * 16 + gid;
                a[mt][0] = __float_as_uint(Qs[rb * SPAD + kk + q4]);
                a[mt][1] = __float_as_uint(Qs[(rb + 8) * SPAD + kk + q4]);
                a[mt][2] = __float_as_uint(Qs[rb * SPAD + kk + q4 + 4]);
                a[mt][3] = __float_as_uint(Qs[(rb + 8) * SPAD + kk + q4 + 4]);
            }
            #pragma unroll
            for (int nt = 0; nt < 2; nt++) {
                const int nb = n0 + nt * 8 + gid;
                bb[nt][0] = __float_as_uint(Ks[buf][nb * SPAD + kk + q4]);
                bb[nt][1] = __float_as_uint(Ks[buf][nb * SPAD + kk + q4 + 4]);
            }
            #pragma unroll
            for (int mt = 0; mt < 2; mt++)
                #pragma unroll
                for (int nt = 0; nt < 2; nt++)
                    MMA_TF32(d[mt][nt], a[mt], bb[nt]);
        }

        #pragma unroll
        for (int mt = 0; mt < 2; mt++) {
            #pragma unroll
            for (int nt = 0; nt < 2; nt++) {
                const int rr = m0 + mt * 16 + gid;
                const int c  = lc + n0 + nt * 8 + q4 * 2;
                float* a0 = attn + ((size_t)h * NP + (r0 + rr)) * NL;
                float* a1 = a0 + 8 * NL;
                if (rr < nr) {
                    if (c >= l0 && c < l1)         a0[c]     = d[mt][nt][0];
                    if (c + 1 >= l0 && c + 1 < l1) a0[c + 1] = d[mt][nt][1];
                }
                if (rr + 8 < nr) {
                    if (c >= l0 && c < l1)         a1[c]     = d[mt][nt][2];
                    if (c + 1 >= l0 && c + 1 < l1) a1[c + 1] = d[mt][nt][3];
                }
            }
        }
        __syncthreads();
    }

    // Softmax over [l0, l1) per row; raw scores are L2-hot.
    #pragma unroll
    for (int rr8 = 0; rr8 < 8; rr8++) {
        const int row = w * 8 + rr8;
        if (row >= nr) continue;
        float* arow = attn + ((size_t)h * NP + (r0 + row)) * NL;

        float mx = -1e30f;
        for (int l = l0 + lane; l < l1; l += 32) mx = fmaxf(mx, arow[l]);
        #pragma unroll
        for (int o = 16; o; o >>= 1) mx = fmaxf(mx, __shfl_xor_sync(0xffffffffu, mx, o));

        float sum = 0.f;
        for (int l = l0 + lane; l < l1; l += 32) {
            const float e = __expf(arow[l] - mx);
            arow[l] = e;
            sum += e;
        }
        #pragma unroll
        for (int o = 16; o; o >>= 1) sum += __shfl_xor_sync(0xffffffffu, sum, o);
        const float inv = 1.f / sum;

        for (int l = l0 + lane; l < l1; l += 32) arow[l] *= inv;
    }
}

// ---------------------------------------------------------------------------
// Context via tf32 mma, cp.async double-buffered P and V staging.
// Chunks aligned to l0 & ~63: P columns outside [l0,l1) are exactly 0 in attn
// (zero-fill + guarded score writes). P rows >= nr left unstaged (garbage
// reaches only discarded D rows). Writes scrambled layout (h*NP+p)*64 + d.
// ---------------------------------------------------------------------------
#define VPAD 72

__global__ void __launch_bounds__(256) ctx_mma(const float* __restrict__ attn,
                                               const float* __restrict__ Vm,
                                               float* __restrict__ ctx)
{
    const int b = g_tile_b[blockIdx.x];
    if (b < 0) return;
    const int r0 = g_tile_r[blockIdx.x];
    const int nr = min(64, g_pend[b] - r0);
    const int l0 = g_lstart[b], l1 = g_lend[b];
    const int h  = blockIdx.y;
    const int al0 = l0 & ~63;
    const int nch = (l1 - al0 + 63) >> 6;

    __shared__ __align__(16) float Ps[2][64 * SPAD];   // [row][l]
    __shared__ __align__(16) float Vs[2][64 * VPAD];   // [l][d]

    const int t = threadIdx.x;
    const int lane = t & 31, w = t >> 5;
    const int wm = w >> 2, wn = w & 3;
    const int m0 = wm * 32, n0 = wn * 16;
    const int gid = lane >> 2, q4 = lane & 3;

    auto stagePV = [&](int buf, int lc) {
        #pragma unroll
        for (int j = 0; j < 4; j++) {
            const int i = t + j * 256;
            const int row = i >> 4, q = (i & 15) * 4;
            if (row < nr)
                cp16(&Ps[buf][row * SPAD + q],
                     attn + ((size_t)h * NP + (r0 + row)) * NL + lc + q);
        }
        #pragma unroll
        for (int j = 0; j < 4; j++) {
            const int i = t + j * 256;
            const int l = i >> 4, q = (i & 15) * 4;
            cp16(&Vs[buf][l * VPAD + q], Vm + (size_t)(lc + l) * DM + h * 64 + q);
        }
    };

    float d[2][2][4] = {};

    stagePV(0, al0);
    CP_COMMIT();

    for (int ch = 0; ch < nch; ch++) {
        const int buf = ch & 1;
        if (ch + 1 < nch) {
            stagePV(buf ^ 1, al0 + (ch + 1) * 64);
            CP_COMMIT();
            CP_WAIT(1);
        } else {
            CP_WAIT(0);
        }
        __syncthreads();

        #pragma unroll
        for (int kk = 0; kk < 64; kk += 8) {
            uint32_t a[2][4], bb[2][2];
            #pragma unroll
            for (int mt = 0; mt < 2; mt++) {
                const int rb = m0 + mt * 16 + gid;
                a[mt][0] = __float_as_uint(Ps[buf][rb * SPAD + kk + q4]);
                a[mt][1] = __float_as_uint(Ps[buf][(rb + 8) * SPAD + kk + q4]);
                a[mt][2] = __float_as_uint(Ps[buf][rb * SPAD + kk + q4 + 4]);
                a[mt][3] = __float_as_uint(Ps[buf][(rb + 8) * SPAD + kk + q4 + 4]);
            }
            #pragma unroll
            for (int nt = 0; nt < 2; nt++) {
                const int nb = n0 + nt * 8 + gid;   // d-column
                bb[nt][0] = __float_as_uint(Vs[buf][(kk + q4) * VPAD + nb]);
                bb[nt][1] = __float_as_uint(Vs[buf][(kk + q4 + 4) * VPAD + nb]);
            }
            #pragma unroll
            for (int mt = 0; mt < 2; mt++)
                #pragma unroll
                for (int nt = 0; nt < 2; nt++)
                    MMA_TF32(d[mt][nt], a[mt], bb[nt]);
        }
        __syncthreads();
    }

    #pragma unroll
    for (int mt = 0; mt < 2; mt++) {
        #pragma unroll
        for (int nt = 0; nt < 2; nt++) {
            const int rr = m0 + mt * 16 + gid;
            const int c  = n0 + nt * 8 + q4 * 2;
            if (rr < nr) {
                float* o = ctx + ((size_t)h * NP + (r0 + rr)) * 64;
                o[c] = d[mt][nt][0]; o[c + 1] = d[mt][nt][1];
            }
            if (rr + 8 < nr) {
                float* o = ctx + ((size_t)h * NP + (r0 + rr + 8)) * 64;
                o[c] = d[mt][nt][2]; o[c + 1] = d[mt][nt][3];
            }
        }
    }
}

// ---------------------------------------------------------------------------
// LayerNorm: warp per row over 512 features.
// ---------------------------------------------------------------------------
__global__ void ln_kernel(const float* __restrict__ X,
                          const float* __restrict__ gamma,
                          const float* __restrict__ beta,
                          float* __restrict__ out)
{
    const int row  = blockIdx.x * 8 + (threadIdx.x >> 5);
    const int lane = threadIdx.x & 31;
    const float* xr = X + (size_t)row * DM;

    float v[16];
    float s = 0.f;
    #pragma unroll
    for (int i = 0; i < 16; i++) { v[i] = xr[lane + i * 32]; s += v[i]; }
    #pragma unroll
    for (int o = 16; o; o >>= 1) s += __shfl_xor_sync(0xffffffffu, s, o);
    const float mu = s * (1.f / 512.f);

    float q = 0.f;
    #pragma unroll
    for (int i = 0; i < 16; i++) { const float d = v[i] - mu; q += d * d; }
    #pragma unroll
    for (int o = 16; o; o >>= 1) q += __shfl_xor_sync(0xffffffffu, q, o);
    const float rstd = rsqrtf(q * (1.f / 512.f) + 1e-5f);

    #pragma unroll
    for (int i = 0; i < 16; i++) {
        const int c = lane + i * 32;
        out[(size_t)row * DM + c] = (v[i] - mu) * rstd * gamma[c] + beta[c];
    }
}

// ---------------------------------------------------------------------------
extern "C" void kernel_launch(void* const* d_in, const int* in_sizes, int n_in,
                              void* d_out, int out_size)
{
    const float* protein = (const float*)d_in[0];
    const float* ligand  = (const float*)d_in[1];
    const int* bp_raw    = (const int*)d_in[2];
    const int* bl_raw    = (const int*)d_in[3];
    const float* Wq = (const float*)d_in[4];
    const float* bq = (const float*)d_in[5];
    const float* Wk = (const float*)d_in[6];
    const float* bk = (const float*)d_in[7];
    const float* Wv = (const float*)d_in[8];
    const float* bv = (const float*)d_in[9];
    const float* Wo = (const float*)d_in[10];
    const float* bo = (const float*)d_in[11];
    const float* gamma = (const float*)d_in[12];
    const float* beta  = (const float*)d_in[13];

    float* out  = (float*)d_out;                      // [4096, 512]
    float* attn = out + (size_t)NP * DM;              // [1, 8, 4096, 2048]

    float *Qp, *Kp, *Vp, *Cp, *Tp;
    cudaGetSymbolAddress((void**)&Qp, g_Q);
    cudaGetSymbolAddress((void**)&Kp, g_K);
    cudaGetSymbolAddress((void**)&Vp, g_V);
    cudaGetSymbolAddress((void**)&Cp, g_ctx);
    cudaGetSymbolAddress((void**)&Tp, g_tmp);

    // Phase 1: Q/K/V projections + attn zero-fill + batch prep, one launch
    p1_kernel<<<256 + 4096 + 1, 256>>>(protein, ligand, bp_raw, bl_raw,
                                       Wq, bq, Wk, bk, Wv, bv,
                                       Qp, Kp, Vp, (float4*)attn);

    // Scores + softmax fused, then context (tensor cores throughout)
    score_sm<<<dim3(MAXT, NH), 256>>>(Qp, Kp, attn);
    ctx_mma<<<dim3(MAXT, NH), 256>>>(attn, Vp, Cp);

    // Output projection + residual, then LayerNorm
    gemm_tf32<<<dim3(DM / 128, NP / 128), 256>>>(Cp, Wo, bo, protein, Tp);
    ln_kernel<<<NP / 8, 256>>>(Tp, gamma, beta, out);
}

// round 17
// speedup vs baseline: 1.2917x; 1.0276x over previous
#include <cuda_runtime.h>
#include <cuda_bf16.h>
#include <cstdint>

#define NP 4096
#define NL 2048
#define DM 512
#define NH 8
#define DK 64
#define NB 16
#define MAXT 80   // max row tiles: 4096/64 + 16

// Scratch (allocation-free rule: __device__ globals)
__device__ float g_Q[NP * DM];
__device__ float g_K[NL * DM];
__device__ float g_V[NL * DM];
__device__ float g_ctx[NP * DM];
__device__ float g_tmp[NP * DM];
__device__ int   g_bp[NP];
__device__ int   g_bl[NL];
__device__ int   g_pstart[NB], g_pend[NB];
__device__ int   g_lstart[NB], g_lend[NB];
__device__ int   g_tile_b[MAXT], g_tile_r[MAXT];

__device__ __forceinline__ float to_tf32(float x) {
    float y;
    asm("cvt.rna.tf32.f32 %0, %1;" : "=f"(y) : "f"(x));
    return y;
}

#define MMA_TF32(d, a, b) \
    asm volatile("mma.sync.aligned.m16n8k8.row.col.f32.tf32.tf32.f32 " \
        "{%0,%1,%2,%3}, {%4,%5,%6,%7}, {%8,%9}, {%0,%1,%2,%3};" \
        : "+f"((d)[0]), "+f"((d)[1]), "+f"((d)[2]), "+f"((d)[3]) \
        : "r"((a)[0]), "r"((a)[1]), "r"((a)[2]), "r"((a)[3]), \
          "r"((b)[0]), "r"((b)[1]))

__device__ __forceinline__ void cp16(void* sdst, const void* gsrc) {
    uint32_t s = (uint32_t)__cvta_generic_to_shared(sdst);
    asm volatile("cp.async.ca.shared.global [%0], [%1], 16;" :: "r"(s), "l"(gsrc) : "memory");
}
#define CP_COMMIT() asm volatile("cp.async.commit_group;" ::: "memory")
#define CP_WAIT(n)  asm volatile("cp.async.wait_group %0;" :: "n"(n) : "memory")

// ---------------------------------------------------------------------------
// tf32 mma GEMM tile, cp.async double-buffered, K-chunk 32 (16 chunks).
// Y[128,128] = X[128,K] W[128,K]^T + bias (+res). 8 warps (2x4), warp 64x32.
// ---------------------------------------------------------------------------
#define GK   32
#define GPAD 36

__device__ __forceinline__ void gemm_tile(const float* __restrict__ X,
                                          const float* __restrict__ W,
                                          const float* __restrict__ bias,
                                          const float* __restrict__ res,
                                          float* __restrict__ Y,
                                          int row0, int col0)
{
    __shared__ __align__(16) float Xs[2][128 * GPAD];
    __shared__ __align__(16) float Ws[2][128 * GPAD];

    const int t = threadIdx.x;
    const int lane = t & 31, w = t >> 5;
    const int wm = w >> 2, wn = w & 3;          // 2 x 4 warp grid
    const int m0 = wm * 64, n0 = wn * 32;       // warp tile 64x32
    const int gid = lane >> 2, q4 = lane & 3;

    float d[4][4][4] = {};

    auto stage = [&](int buf, int k0) {
        #pragma unroll
        for (int j = 0; j < 4; j++) {
            const int f = t + j * 256;           // 0..1023
            const int r = f >> 3, q = (f & 7) * 4;
            cp16(&Xs[buf][r * GPAD + q], X + (size_t)(row0 + r) * DM + k0 + q);
            cp16(&Ws[buf][r * GPAD + q], W + (size_t)(col0 + r) * DM + k0 + q);
        }
    };

    const int NCH = DM / GK;   // 16 chunks
    stage(0, 0);
    CP_COMMIT();

    for (int kc = 0; kc < NCH; kc++) {
        const int buf = kc & 1;
        if (kc + 1 < NCH) {
            stage(buf ^ 1, (kc + 1) * GK);
            CP_COMMIT();
            CP_WAIT(1);
        } else {
            CP_WAIT(0);
        }
        __syncthreads();

        #pragma unroll
        for (int kk = 0; kk < GK; kk += 8) {
            uint32_t a[4][4], b[4][2];
            #pragma unroll
            for (int mt = 0; mt < 4; mt++) {
                const int rb = m0 + mt * 16 + gid;
                a[mt][0] = __float_as_uint(Xs[buf][rb * GPAD + kk + q4]);
                a[mt][1] = __float_as_uint(Xs[buf][(rb + 8) * GPAD + kk + q4]);
                a[mt][2] = __float_as_uint(Xs[buf][rb * GPAD + kk + q4 + 4]);
                a[mt][3] = __float_as_uint(Xs[buf][(rb + 8) * GPAD + kk + q4 + 4]);
            }
            #pragma unroll
            for (int nt = 0; nt < 4; nt++) {
                const int nb = n0 + nt * 8 + gid;
                b[nt][0] = __float_as_uint(Ws[buf][nb * GPAD + kk + q4]);
                b[nt][1] = __float_as_uint(Ws[buf][nb * GPAD + kk + q4 + 4]);
            }
            #pragma unroll
            for (int mt = 0; mt < 4; mt++)
                #pragma unroll
                for (int nt = 0; nt < 4; nt++)
                    MMA_TF32(d[mt][nt], a[mt], b[nt]);
        }
        __syncthreads();
    }

    #pragma unroll
    for (int mt = 0; mt < 4; mt++) {
        #pragma unroll
        for (int nt = 0; nt < 4; nt++) {
            const int r1 = row0 + m0 + mt * 16 + gid;
            const int c  = col0 + n0 + nt * 8 + q4 * 2;
            const float b0 = bias[c], b1 = bias[c + 1];
            float2 o0 = make_float2(d[mt][nt][0] + b0, d[mt][nt][1] + b1);
            float2 o1 = make_float2(d[mt][nt][2] + b0, d[mt][nt][3] + b1);
            if (res) {
                const float2 r0v = *reinterpret_cast<const float2*>(res + (size_t)r1 * DM + c);
                const float2 r1v = *reinterpret_cast<const float2*>(res + (size_t)(r1 + 8) * DM + c);
                o0.x += r0v.x; o0.y += r0v.y;
                o1.x += r1v.x; o1.y += r1v.y;
            }
            *reinterpret_cast<float2*>(Y + (size_t)r1 * DM + c) = o0;
            *reinterpret_cast<float2*>(Y + (size_t)(r1 + 8) * DM + c) = o1;
        }
    }
}

// ---------------------------------------------------------------------------
// Phase 1: Q/K/V projections (256 CTAs, 128x128 tiles) + batch prep (1 CTA).
// The attn zero-fill now lives inside score_sm (overlapped with its compute).
// ---------------------------------------------------------------------------
__global__ void __launch_bounds__(256) p1_kernel(
    const float* __restrict__ protein, const float* __restrict__ ligand,
    const int* __restrict__ bpraw, const int* __restrict__ blraw,
    const float* __restrict__ Wq, const float* __restrict__ bq,
    const float* __restrict__ Wk, const float* __restrict__ bk,
    const float* __restrict__ Wv, const float* __restrict__ bv,
    float* __restrict__ Qp, float* __restrict__ Kp, float* __restrict__ Vp)
{
    const int bx = blockIdx.x;
    const int t = threadIdx.x;
    if (bx < 256) {
        const float *X, *W, *bias; float* Y; int lb;
        if (bx < 128)      { X = protein; W = Wq; bias = bq; Y = Qp; lb = bx; }
        else if (bx < 192) { X = ligand;  W = Wk; bias = bk; Y = Kp; lb = bx - 128; }
        else               { X = ligand;  W = Wv; bias = bv; Y = Vp; lb = bx - 192; }
        gemm_tile(X, W, bias, nullptr, Y, (lb >> 2) * 128, (lb & 3) * 128);
    } else {
        // prep: batch arrays -> int32, ranges, tile worklist.
        const int is32p = (bpraw[NP - 1] != 0);
        const int is32l = (blraw[NL - 1] != 0);
        if (t < NB) { g_pstart[t] = 0; g_pend[t] = 0; g_lstart[t] = 0; g_lend[t] = 0; }
        for (int i = t; i < NP; i += 256) g_bp[i] = is32p ? bpraw[i] : bpraw[2 * i];
        for (int i = t; i < NL; i += 256) g_bl[i] = is32l ? blraw[i] : blraw[2 * i];
        __syncthreads();
        for (int i = t; i < NP; i += 256) {
            const int b = g_bp[i];
            if (i == 0 || g_bp[i - 1] != b) g_pstart[b] = i;
            if (i == NP - 1 || g_bp[i + 1] != b) g_pend[b] = i + 1;
        }
        for (int i = t; i < NL; i += 256) {
            const int b = g_bl[i];
            if (i == 0 || g_bl[i - 1] != b) g_lstart[b] = i;
            if (i == NL - 1 || g_bl[i + 1] != b) g_lend[b] = i + 1;
        }
        __syncthreads();
        if (t == 0) {
            int idx = 0;
            for (int b = 0; b < NB; b++)
                for (int r = g_pstart[b]; r < g_pend[b]; r += 64) {
                    g_tile_b[idx] = b; g_tile_r[idx] = r; idx++;
                }
            for (; idx < MAXT; idx++) g_tile_b[idx] = -1;
        }
    }
}

// Standalone GEMM wrapper (output projection).
__global__ void __launch_bounds__(256) gemm_tf32(const float* __restrict__ X,
                                                 const float* __restrict__ W,
                                                 const float* __restrict__ bias,
                                                 const float* __restrict__ res,
                                                 float* __restrict__ Y)
{
    gemm_tile(X, W, bias, res, Y, blockIdx.y * 128, blockIdx.x * 128);
}

// ---------------------------------------------------------------------------
// Scores + softmax + zero-fill fused: per (row-tile 64, head).
// Each CTA exclusively owns its 64 attn rows for head h (tiles partition
// protein rows). After softmax it zero-fills [0,l0) and [l1,NL) per row with
// float4 stores (scalar only at boundary quads, out-of-range columns only) —
// masked entries are exactly 0.0 in the reference (exp underflow).
// ---------------------------------------------------------------------------
#define SPAD 68

__global__ void __launch_bounds__(256) score_sm(const float* __restrict__ Q,
                                                const float* __restrict__ Km,
                                                float* __restrict__ attn)
{
    const int b = g_tile_b[blockIdx.x];
    if (b < 0) return;
    const int r0 = g_tile_r[blockIdx.x];
    const int nr = min(64, g_pend[b] - r0);
    const int l0 = g_lstart[b], l1 = g_lend[b];
    const int h  = blockIdx.y;
    const int al0 = l0 & ~63;
    const int nch = (l1 - al0 + 63) >> 6;

    __shared__ __align__(16) float Qs[64 * SPAD];        // [row][k], prescaled
    __shared__ __align__(16) float Ks[2][64 * SPAD];     // [key][k] double buf

    const int t = threadIdx.x;
    const int lane = t & 31, w = t >> 5;
    const int wm = w >> 2, wn = w & 3;
    const int m0 = wm * 32, n0 = wn * 16;
    const int gid = lane >> 2, q4 = lane & 3;

    auto stageK = [&](int buf, int lc) {
        #pragma unroll
        for (int j = 0; j < 4; j++) {
            const int i = t + j * 256;               // 0..1023
            const int col = i >> 4, q = (i & 15) * 4;
            cp16(&Ks[buf][col * SPAD + q], Km + (size_t)(lc + col) * DM + h * 64 + q);
        }
    };

    stageK(0, al0);
    CP_COMMIT();

    // Q staging (scaled, tf32-rounded) overlaps with first K chunk in flight
    #pragma unroll
    for (int i = t; i < 1024; i += 256) {
        const int row = i >> 4, q = (i & 15) * 4;
        float4 v = make_float4(0.f, 0.f, 0.f, 0.f);
        if (row < nr)
            v = *reinterpret_cast<const float4*>(Q + (size_t)(r0 + row) * DM + h * 64 + q);
        v.x = to_tf32(v.x * 0.125f); v.y = to_tf32(v.y * 0.125f);
        v.z = to_tf32(v.z * 0.125f); v.w = to_tf32(v.w * 0.125f);
        *reinterpret_cast<float4*>(&Qs[row * SPAD + q]) = v;
    }

    for (int ch = 0; ch < nch; ch++) {
        const int lc = al0 + ch * 64;
        const int buf = ch & 1;
        if (ch + 1 < nch) {
            stageK(buf ^ 1, lc + 64);
            CP_COMMIT();
            CP_WAIT(1);
        } else {
            CP_WAIT(0);
        }
        __syncthreads();

        float d[2][2][4] = {};
        #pragma unroll
        for (int kk = 0; kk < 64; kk += 8) {
            uint32_t a[2][4], bb[2][2];
            #pragma unroll
            for (int mt = 0; mt < 2; mt++) {
                const int rb = m0 + mt * 16 + gid;
                a[mt][0] = __float_as_uint(Qs[rb * SPAD + kk + q4]);
                a[mt][1] = __float_as_uint(Qs[(rb + 8) * SPAD + kk + q4]);
                a[mt][2] = __float_as_uint(Qs[rb * SPAD + kk + q4 + 4]);
                a[mt][3] = __float_as_uint(Qs[(rb + 8) * SPAD + kk + q4 + 4]);
            }
            #pragma unroll
            for (int nt = 0; nt < 2; nt++) {
                const int nb = n0 + nt * 8 + gid;
                bb[nt][0] = __float_as_uint(Ks[buf][nb * SPAD + kk + q4]);
                bb[nt][1] = __float_as_uint(Ks[buf][nb * SPAD + kk + q4 + 4]);
            }
            #pragma unroll
            for (int mt = 0; mt < 2; mt++)
                #pragma unroll
                for (int nt = 0; nt < 2; nt++)
                    MMA_TF32(d[mt][nt], a[mt], bb[nt]);
        }

        #pragma unroll
        for (int mt = 0; mt < 2; mt++) {
            #pragma unroll
            for (int nt = 0; nt < 2; nt++) {
                const int rr = m0 + mt * 16 + gid;
                const int c  = lc + n0 + nt * 8 + q4 * 2;
                float* a0 = attn + ((size_t)h * NP + (r0 + rr)) * NL;
                float* a1 = a0 + 8 * NL;
                if (rr < nr) {
                    if (c >= l0 && c < l1)         a0[c]     = d[mt][nt][0];
                    if (c + 1 >= l0 && c + 1 < l1) a0[c + 1] = d[mt][nt][1];
                }
                if (rr + 8 < nr) {
                    if (c >= l0 && c < l1)         a1[c]     = d[mt][nt][2];
                    if (c + 1 >= l0 && c + 1 < l1) a1[c + 1] = d[mt][nt][3];
                }
            }
        }
        __syncthreads();
    }

    // Softmax over [l0, l1) per row + zero-fill of the masked region.
    const float4 zero4 = make_float4(0.f, 0.f, 0.f, 0.f);
    const int jl = l0 >> 2;              // float4s [0, jl) fully left of range
    const int jr = (l1 + 3) >> 2;        // float4s [jr, NL/4) fully right
    #pragma unroll
    for (int rr8 = 0; rr8 < 8; rr8++) {
        const int row = w * 8 + rr8;
        if (row >= nr) continue;
        float* arow = attn + ((size_t)h * NP + (r0 + row)) * NL;

        float mx = -1e30f;
        for (int l = l0 + lane; l < l1; l += 32) mx = fmaxf(mx, arow[l]);
        #pragma unroll
        for (int o = 16; o; o >>= 1) mx = fmaxf(mx, __shfl_xor_sync(0xffffffffu, mx, o));

        float sum = 0.f;
        for (int l = l0 + lane; l < l1; l += 32) {
            const float e = __expf(arow[l] - mx);
            arow[l] = e;
            sum += e;
        }
        #pragma unroll
        for (int o = 16; o; o >>= 1) sum += __shfl_xor_sync(0xffffffffu, sum, o);
        const float inv = 1.f / sum;

        for (int l = l0 + lane; l < l1; l += 32) arow[l] *= inv;

        // Zero-fill masked region (exactly 0.0 in reference).
        float4* r4 = reinterpret_cast<float4*>(arow);
        for (int j = lane; j < jl; j += 32) r4[j] = zero4;
        for (int j = jr + lane; j < NL / 4; j += 32) r4[j] = zero4;
        if (lane < 4) {                      // left boundary quad
            const int c = jl * 4 + lane;
            if (c < l0) arow[c] = 0.f;
        } else if (lane < 8) {               // right boundary quad
            const int c = (l1 & ~3) + (lane - 4);
            if (c >= l1 && c < NL) arow[c] = 0.f;
        }
    }
}

// ---------------------------------------------------------------------------
// Context via tf32 mma, cp.async double-buffered P and V staging.
// Chunks aligned to l0 & ~63: P columns outside [l0,l1) are exactly 0 in attn
// (zero-fill in score_sm). P rows >= nr left unstaged (garbage reaches only
// discarded D rows). Writes scrambled layout (h*NP+p)*64 + d.
// ---------------------------------------------------------------------------
#define VPAD 72

__global__ void __launch_bounds__(256) ctx_mma(const float* __restrict__ attn,
                                               const float* __restrict__ Vm,
                                               float* __restrict__ ctx)
{
    const int b = g_tile_b[blockIdx.x];
    if (b < 0) return;
    const int r0 = g_tile_r[blockIdx.x];
    const int nr = min(64, g_pend[b] - r0);
    const int l0 = g_lstart[b], l1 = g_lend[b];
    const int h  = blockIdx.y;
    const int al0 = l0 & ~63;
    const int nch = (l1 - al0 + 63) >> 6;

    __shared__ __align__(16) float Ps[2][64 * SPAD];   // [row][l]
    __shared__ __align__(16) float Vs[2][64 * VPAD];   // [l][d]

    const int t = threadIdx.x;
    const int lane = t & 31, w = t >> 5;
    const int wm = w >> 2, wn = w & 3;
    const int m0 = wm * 32, n0 = wn * 16;
    const int gid = lane >> 2, q4 = lane & 3;

    auto stagePV = [&](int buf, int lc) {
        #pragma unroll
        for (int j = 0; j < 4; j++) {
            const int i = t + j * 256;
            const int row = i >> 4, q = (i & 15) * 4;
            if (row < nr)
                cp16(&Ps[buf][row * SPAD + q],
                     attn + ((size_t)h * NP + (r0 + row)) * NL + lc + q);
        }
        #pragma unroll
        for (int j = 0; j < 4; j++) {
            const int i = t + j * 256;
            const int l = i >> 4, q = (i & 15) * 4;
            cp16(&Vs[buf][l * VPAD + q], Vm + (size_t)(lc + l) * DM + h * 64 + q);
        }
    };

    float d[2][2][4] = {};

    stagePV(0, al0);
    CP_COMMIT();

    for (int ch = 0; ch < nch; ch++) {
        const int buf = ch & 1;
        if (ch + 1 < nch) {
            stagePV(buf ^ 1, al0 + (ch + 1) * 64);
            CP_COMMIT();
            CP_WAIT(1);
        } else {
            CP_WAIT(0);
        }
        __syncthreads();

        #pragma unroll
        for (int kk = 0; kk < 64; kk += 8) {
            uint32_t a[2][4], bb[2][2];
            #pragma unroll
            for (int mt = 0; mt < 2; mt++) {
                const int rb = m0 + mt * 16 + gid;
                a[mt][0] = __float_as_uint(Ps[buf][rb * SPAD + kk + q4]);
                a[mt][1] = __float_as_uint(Ps[buf][(rb + 8) * SPAD + kk + q4]);
                a[mt][2] = __float_as_uint(Ps[buf][rb * SPAD + kk + q4 + 4]);
                a[mt][3] = __float_as_uint(Ps[buf][(rb + 8) * SPAD + kk + q4 + 4]);
            }
            #pragma unroll
            for (int nt = 0; nt < 2; nt++) {
                const int nb = n0 + nt * 8 + gid;   // d-column
                bb[nt][0] = __float_as_uint(Vs[buf][(kk + q4) * VPAD + nb]);
                bb[nt][1] = __float_as_uint(Vs[buf][(kk + q4 + 4) * VPAD + nb]);
            }
            #pragma unroll
            for (int mt = 0; mt < 2; mt++)
                #pragma unroll
                for (int nt = 0; nt < 2; nt++)
                    MMA_TF32(d[mt][nt], a[mt], bb[nt]);
        }
        __syncthreads();
    }

    #pragma unroll
    for (int mt = 0; mt < 2; mt++) {
        #pragma unroll
        for (int nt = 0; nt < 2; nt++) {
            const int rr = m0 + mt * 16 + gid;
            const int c  = n0 + nt * 8 + q4 * 2;
            if (rr < nr) {
                float* o = ctx + ((size_t)h * NP + (r0 + rr)) * 64;
                o[c] = d[mt][nt][0]; o[c + 1] = d[mt][nt][1];
            }
            if (rr + 8 < nr) {
                float* o = ctx + ((size_t)h * NP + (r0 + rr + 8)) * 64;
                o[c] = d[mt][nt][2]; o[c + 1] = d[mt][nt][3];
            }
        }
    }
}

// ---------------------------------------------------------------------------
// LayerNorm: warp per row over 512 features.
// ---------------------------------------------------------------------------
__global__ void ln_kernel(const float* __restrict__ X,
                          const float* __restrict__ gamma,
                          const float* __restrict__ beta,
                          float* __restrict__ out)
{
    const int row  = blockIdx.x * 8 + (threadIdx.x >> 5);
    const int lane = threadIdx.x & 31;
    const float* xr = X + (size_t)row * DM;

    float v[16];
    float s = 0.f;
    #pragma unroll
    for (int i = 0; i < 16; i++) { v[i] = xr[lane + i * 32]; s += v[i]; }
    #pragma unroll
    for (int o = 16; o; o >>= 1) s += __shfl_xor_sync(0xffffffffu, s, o);
    const float mu = s * (1.f / 512.f);

    float q = 0.f;
    #pragma unroll
    for (int i = 0; i < 16; i++) { const float d = v[i] - mu; q += d * d; }
    #pragma unroll
    for (int o = 16; o; o >>= 1) q += __shfl_xor_sync(0xffffffffu, q, o);
    const float rstd = rsqrtf(q * (1.f / 512.f) + 1e-5f);

    #pragma unroll
    for (int i = 0; i < 16; i++) {
        const int c = lane + i * 32;
        out[(size_t)row * DM + c] = (v[i] - mu) * rstd * gamma[c] + beta[c];
    }
}

// ---------------------------------------------------------------------------
extern "C" void kernel_launch(void* const* d_in, const int* in_sizes, int n_in,
                              void* d_out, int out_size)
{
    const float* protein = (const float*)d_in[0];
    const float* ligand  = (const float*)d_in[1];
    const int* bp_raw    = (const int*)d_in[2];
    const int* bl_raw    = (const int*)d_in[3];
    const float* Wq = (const float*)d_in[4];
    const float* bq = (const float*)d_in[5];
    const float* Wk = (const float*)d_in[6];
    const float* bk = (const float*)d_in[7];
    const float* Wv = (const float*)d_in[8];
    const float* bv = (const float*)d_in[9];
    const float* Wo = (const float*)d_in[10];
    const float* bo = (const float*)d_in[11];
    const float* gamma = (const float*)d_in[12];
    const float* beta  = (const float*)d_in[13];

    float* out  = (float*)d_out;                      // [4096, 512]
    float* attn = out + (size_t)NP * DM;              // [1, 8, 4096, 2048]

    float *Qp, *Kp, *Vp, *Cp, *Tp;
    cudaGetSymbolAddress((void**)&Qp, g_Q);
    cudaGetSymbolAddress((void**)&Kp, g_K);
    cudaGetSymbolAddress((void**)&Vp, g_V);
    cudaGetSymbolAddress((void**)&Cp, g_ctx);
    cudaGetSymbolAddress((void**)&Tp, g_tmp);

    // Phase 1: Q/K/V projections + batch prep (zero-fill folded into score_sm)
    p1_kernel<<<256 + 1, 256>>>(protein, ligand, bp_raw, bl_raw,
                                Wq, bq, Wk, bk, Wv, bv, Qp, Kp, Vp);

    // Scores + softmax + zero-fill fused, then context
    score_sm<<<dim3(MAXT, NH), 256>>>(Qp, Kp, attn);
    ctx_mma<<<dim3(MAXT, NH), 256>>>(attn, Vp, Cp);

    // Output projection + residual, then LayerNorm
    gemm_tf32<<<dim3(DM / 128, NP / 128), 256>>>(Cp, Wo, bo, protein, Tp);
    ln_kernel<<<NP / 8, 256>>>(Tp, gamma, beta, out);
}